// round 3
// baseline (speedup 1.0000x reference)
#include <cuda_runtime.h>

#define N_NODES 100000
#define N_EDGES 1600000
#define IN_DIM 128
#define OUT_DIM 64
#define NEG_SLOPE 0.2f

// ---------------- scratch (device globals: no allocations allowed) ----------
__device__ __align__(16) float g_Wh[N_NODES * OUT_DIM];   // 25.6 MB
__device__ float g_ssrc[N_NODES];
__device__ float g_sdst[N_NODES];
__device__ float g_denom[N_NODES];
__device__ float g_expe[N_EDGES];
__device__ unsigned g_maxenc;

// monotone encoding of float for unsigned atomicMax
__device__ __forceinline__ unsigned enc_f(float f) {
    unsigned u = __float_as_uint(f);
    return (u & 0x80000000u) ? ~u : (u | 0x80000000u);
}
__device__ __forceinline__ float dec_f(unsigned e) {
    unsigned u = (e & 0x80000000u) ? (e ^ 0x80000000u) : ~e;
    return __uint_as_float(u);
}

// ---------------- K0: zero output, denom, max --------------------------------
__global__ void k_init(float4* __restrict__ out4) {
    int i = blockIdx.x * blockDim.x + threadIdx.x;   // 6250*256 = 1.6M float4 = 6.4M floats
    out4[i] = make_float4(0.f, 0.f, 0.f, 0.f);
    if (i < N_NODES) g_denom[i] = 0.f;
    if (i == 0) g_maxenc = 0u;
}

// ---------------- K1: Wh = h @ W, fused s_src/s_dst ---------------------------
// Block 256 threads, tile of 128 nodes. Each thread: 4 nodes x 8 outputs.
#define K1_BLOCK 256
#define NODE_TILE 128
#define KCH 16

__global__ __launch_bounds__(K1_BLOCK)
void k_gemm(const float* __restrict__ h, const float* __restrict__ W,
            const float* __restrict__ a) {
    __shared__ __align__(16) float Ws[IN_DIM * OUT_DIM];          // 32 KB
    __shared__ float hs[NODE_TILE * (KCH + 1)];                    // 8.7 KB, pad vs conflicts
    __shared__ float as[2 * OUT_DIM];

    int tid = threadIdx.x;
    for (int i = tid; i < IN_DIM * OUT_DIM; i += K1_BLOCK) Ws[i] = W[i];
    if (tid < 2 * OUT_DIM) as[tid] = a[tid];

    int base = blockIdx.x * NODE_TILE;
    int nr = tid >> 3;             // 0..31
    int jc = (tid & 7) * 8;        // 0..56

    float acc[4][8];
#pragma unroll
    for (int i = 0; i < 4; i++)
#pragma unroll
        for (int q = 0; q < 8; q++) acc[i][q] = 0.f;

    for (int k0 = 0; k0 < IN_DIM; k0 += KCH) {
        __syncthreads();
        for (int i = tid; i < NODE_TILE * KCH; i += K1_BLOCK) {
            int nl = i >> 4, kk = i & 15;
            int gn = base + nl;
            hs[nl * (KCH + 1) + kk] = (gn < N_NODES) ? h[(size_t)gn * IN_DIM + k0 + kk] : 0.f;
        }
        __syncthreads();
#pragma unroll
        for (int kk = 0; kk < KCH; kk++) {
            float4 w0 = *(const float4*)&Ws[(k0 + kk) * OUT_DIM + jc];
            float4 w1 = *(const float4*)&Ws[(k0 + kk) * OUT_DIM + jc + 4];
#pragma unroll
            for (int i = 0; i < 4; i++) {
                float hk = hs[(nr + 32 * i) * (KCH + 1) + kk];
                acc[i][0] += hk * w0.x; acc[i][1] += hk * w0.y;
                acc[i][2] += hk * w0.z; acc[i][3] += hk * w0.w;
                acc[i][4] += hk * w1.x; acc[i][5] += hk * w1.y;
                acc[i][6] += hk * w1.z; acc[i][7] += hk * w1.w;
            }
        }
    }

#pragma unroll
    for (int i = 0; i < 4; i++) {
        int n = base + nr + 32 * i;
        float ps = 0.f, pd = 0.f;
#pragma unroll
        for (int q = 0; q < 8; q++) {
            ps += acc[i][q] * as[jc + q];
            pd += acc[i][q] * as[OUT_DIM + jc + q];
        }
        // reduce across the 8 consecutive lanes sharing this node
        for (int off = 4; off > 0; off >>= 1) {
            ps += __shfl_down_sync(0xFFFFFFFFu, ps, off, 8);
            pd += __shfl_down_sync(0xFFFFFFFFu, pd, off, 8);
        }
        if (n < N_NODES) {
            *(float4*)&g_Wh[(size_t)n * OUT_DIM + jc] =
                make_float4(acc[i][0], acc[i][1], acc[i][2], acc[i][3]);
            *(float4*)&g_Wh[(size_t)n * OUT_DIM + jc + 4] =
                make_float4(acc[i][4], acc[i][5], acc[i][6], acc[i][7]);
            if ((tid & 7) == 0) { g_ssrc[n] = ps; g_sdst[n] = pd; }
        }
    }
}

// ---------------- K2: global max of leaky_relu(s_src[row]+s_dst[col]) --------
__global__ void k_max(const int* __restrict__ row,
                      const int* __restrict__ col) {
    int e = blockIdx.x * blockDim.x + threadIdx.x;
    float ev = -3.4e38f;
    if (e < N_EDGES) {
        int r = row[e], c = col[e];
        float x = g_ssrc[r] + g_sdst[c];
        ev = x > 0.f ? x : NEG_SLOPE * x;
    }
    unsigned m = enc_f(ev);
    for (int off = 16; off > 0; off >>= 1)
        m = max(m, __shfl_down_sync(0xFFFFFFFFu, m, off));
    __shared__ unsigned sm[8];
    if ((threadIdx.x & 31) == 0) sm[threadIdx.x >> 5] = m;
    __syncthreads();
    if (threadIdx.x == 0) {
        unsigned mm = sm[0];
#pragma unroll
        for (int i = 1; i < 8; i++) mm = max(mm, sm[i]);
        atomicMax(&g_maxenc, mm);
    }
}

// ---------------- K3: exp(e - M), denominator segment sum --------------------
__global__ void k_expdenom(const int* __restrict__ row,
                           const int* __restrict__ col) {
    int e = blockIdx.x * blockDim.x + threadIdx.x;
    if (e >= N_EDGES) return;
    float M = dec_f(g_maxenc);
    int r = row[e], c = col[e];
    float x = g_ssrc[r] + g_sdst[c];
    float ev = x > 0.f ? x : NEG_SLOPE * x;
    float ex = __expf(ev - M);
    g_expe[e] = ex;
    atomicAdd(&g_denom[r], ex);
}

// ---------------- K4: out[row] += alpha * Wh[col]  (scalar red) ---------------
// 16 lanes per edge, each lane owns one float4 of Wh -> 4 scalar atomic adds.
__global__ __launch_bounds__(256)
void k_scatter(const int* __restrict__ row,
               const int* __restrict__ col,
               float* __restrict__ out) {
    int team = (blockIdx.x * blockDim.x + threadIdx.x) >> 4;
    int lane = threadIdx.x & 15;
    if (team >= N_EDGES) return;
    int r = row[team];
    int c = col[team];
    float alpha = g_expe[team] / (g_denom[r] + 1e-10f);
    float4 v = *(const float4*)&g_Wh[(size_t)c * OUT_DIM + lane * 4];
    float* dst = out + (size_t)r * OUT_DIM + lane * 4;
    atomicAdd(dst + 0, alpha * v.x);
    atomicAdd(dst + 1, alpha * v.y);
    atomicAdd(dst + 2, alpha * v.z);
    atomicAdd(dst + 3, alpha * v.w);
}

// ---------------- launch ------------------------------------------------------
extern "C" void kernel_launch(void* const* d_in, const int* in_sizes, int n_in,
                              void* d_out, int out_size) {
    const float* h = (const float*)d_in[0];
    const int* row = (const int*)d_in[1];
    const int* col = (const int*)d_in[2];
    const float* W = (const float*)d_in[3];
    const float* a = (const float*)d_in[4];
    float* out = (float*)d_out;

    k_init<<<6250, 256>>>((float4*)out);                       // 1.6M float4
    k_gemm<<<(N_NODES + NODE_TILE - 1) / NODE_TILE, K1_BLOCK>>>(h, W, a);
    k_max<<<N_EDGES / 256, 256>>>(row, col);                   // 6250 blocks
    k_expdenom<<<N_EDGES / 256, 256>>>(row, col);
    k_scatter<<<N_EDGES * 16 / 256, 256>>>(row, col, out);     // 100000 blocks
}

// round 4
// speedup vs baseline: 1.9076x; 1.9076x over previous
#include <cuda_runtime.h>

#define N_NODES 100000
#define N_EDGES 1600000
#define IN_DIM 128
#define OUT_DIM 64
#define NEG_SLOPE 0.2f

// ---------------- scratch (device globals: no allocations allowed) ----------
__device__ __align__(16) float g_Wh[N_NODES * OUT_DIM];   // 25.6 MB
__device__ float g_ssrc[N_NODES];
__device__ float g_sdst[N_NODES];
__device__ int   g_cnt[N_NODES];       // degree (by row)
__device__ int   g_rowstart[N_NODES];  // CSR offsets (exclusive scan of cnt)
__device__ int   g_cursor[N_NODES];    // fill cursors
__device__ int   g_bsum[128];          // block sums for scan
__device__ int   g_colp[N_EDGES];      // col, row-sorted
__device__ float g_expp[N_EDGES];      // exp(e), row-sorted

// ---------------- K0: zero histogram ----------------------------------------
__global__ void k_init() {
    int i = blockIdx.x * blockDim.x + threadIdx.x;
    if (i < N_NODES) g_cnt[i] = 0;
}

// ---------------- K1: Wh = h @ W, fused s_src/s_dst ---------------------------
#define K1_BLOCK 256
#define NODE_TILE 128
#define KCH 16

__global__ __launch_bounds__(K1_BLOCK)
void k_gemm(const float* __restrict__ h, const float* __restrict__ W,
            const float* __restrict__ a) {
    __shared__ __align__(16) float Ws[IN_DIM * OUT_DIM];
    __shared__ float hs[NODE_TILE * (KCH + 1)];
    __shared__ float as[2 * OUT_DIM];

    int tid = threadIdx.x;
    for (int i = tid; i < IN_DIM * OUT_DIM; i += K1_BLOCK) Ws[i] = W[i];
    if (tid < 2 * OUT_DIM) as[tid] = a[tid];

    int base = blockIdx.x * NODE_TILE;
    int nr = tid >> 3;
    int jc = (tid & 7) * 8;

    float acc[4][8];
#pragma unroll
    for (int i = 0; i < 4; i++)
#pragma unroll
        for (int q = 0; q < 8; q++) acc[i][q] = 0.f;

    for (int k0 = 0; k0 < IN_DIM; k0 += KCH) {
        __syncthreads();
        for (int i = tid; i < NODE_TILE * KCH; i += K1_BLOCK) {
            int nl = i >> 4, kk = i & 15;
            int gn = base + nl;
            hs[nl * (KCH + 1) + kk] = (gn < N_NODES) ? h[(size_t)gn * IN_DIM + k0 + kk] : 0.f;
        }
        __syncthreads();
#pragma unroll
        for (int kk = 0; kk < KCH; kk++) {
            float4 w0 = *(const float4*)&Ws[(k0 + kk) * OUT_DIM + jc];
            float4 w1 = *(const float4*)&Ws[(k0 + kk) * OUT_DIM + jc + 4];
#pragma unroll
            for (int i = 0; i < 4; i++) {
                float hk = hs[(nr + 32 * i) * (KCH + 1) + kk];
                acc[i][0] += hk * w0.x; acc[i][1] += hk * w0.y;
                acc[i][2] += hk * w0.z; acc[i][3] += hk * w0.w;
                acc[i][4] += hk * w1.x; acc[i][5] += hk * w1.y;
                acc[i][6] += hk * w1.z; acc[i][7] += hk * w1.w;
            }
        }
    }

#pragma unroll
    for (int i = 0; i < 4; i++) {
        int n = base + nr + 32 * i;
        float ps = 0.f, pd = 0.f;
#pragma unroll
        for (int q = 0; q < 8; q++) {
            ps += acc[i][q] * as[jc + q];
            pd += acc[i][q] * as[OUT_DIM + jc + q];
        }
        for (int off = 4; off > 0; off >>= 1) {
            ps += __shfl_down_sync(0xFFFFFFFFu, ps, off, 8);
            pd += __shfl_down_sync(0xFFFFFFFFu, pd, off, 8);
        }
        if (n < N_NODES) {
            *(float4*)&g_Wh[(size_t)n * OUT_DIM + jc] =
                make_float4(acc[i][0], acc[i][1], acc[i][2], acc[i][3]);
            *(float4*)&g_Wh[(size_t)n * OUT_DIM + jc + 4] =
                make_float4(acc[i][4], acc[i][5], acc[i][6], acc[i][7]);
            if ((tid & 7) == 0) { g_ssrc[n] = ps; g_sdst[n] = pd; }
        }
    }
}

// ---------------- K2: histogram of row ---------------------------------------
__global__ void k_hist(const int* __restrict__ row) {
    int e = blockIdx.x * blockDim.x + threadIdx.x;
    if (e < N_EDGES) atomicAdd(&g_cnt[row[e]], 1);
}

// ---------------- K3a: per-block inclusive scan -------------------------------
__global__ __launch_bounds__(1024)
void k_scan1() {
    __shared__ int sh[1024];
    int i = blockIdx.x * 1024 + threadIdx.x;
    int v = (i < N_NODES) ? g_cnt[i] : 0;
    sh[threadIdx.x] = v;
    __syncthreads();
    for (int off = 1; off < 1024; off <<= 1) {
        int t = (threadIdx.x >= off) ? sh[threadIdx.x - off] : 0;
        __syncthreads();
        sh[threadIdx.x] += t;
        __syncthreads();
    }
    if (i < N_NODES) g_rowstart[i] = sh[threadIdx.x];   // inclusive, block-local
    if (threadIdx.x == 1023) g_bsum[blockIdx.x] = sh[1023];
}

// ---------------- K3b: scan the 98 block sums (exclusive) ---------------------
__global__ void k_scan2(int nblocks) {
    if (threadIdx.x == 0 && blockIdx.x == 0) {
        int run = 0;
        for (int b = 0; b < nblocks; b++) {
            int t = g_bsum[b];
            g_bsum[b] = run;
            run += t;
        }
    }
}

// ---------------- K3c: finalize exclusive offsets + cursors -------------------
__global__ void k_scan3() {
    int i = blockIdx.x * blockDim.x + threadIdx.x;
    if (i >= N_NODES) return;
    int start = g_rowstart[i] - g_cnt[i] + g_bsum[i >> 10];
    g_rowstart[i] = start;
    g_cursor[i] = start;
}

// ---------------- K4: compute exp(e), fill row-sorted (col, exp) --------------
__global__ void k_fill(const int* __restrict__ row,
                       const int* __restrict__ col) {
    int e = blockIdx.x * blockDim.x + threadIdx.x;
    if (e >= N_EDGES) return;
    int r = row[e], c = col[e];
    float x = g_ssrc[r] + g_sdst[c];
    float ev = x > 0.f ? x : NEG_SLOPE * x;
    float ex = __expf(ev);          // max-shift cancels in alpha; |ev| small
    int pos = atomicAdd(&g_cursor[r], 1);
    g_colp[pos] = c;
    g_expp[pos] = ex;
}

// ---------------- K5: warp-per-node gather accumulation (no atomics) ----------
__global__ __launch_bounds__(256)
void k_accum(float* __restrict__ out) {
    int node = (blockIdx.x * blockDim.x + threadIdx.x) >> 5;
    int lane = threadIdx.x & 31;
    if (node >= N_NODES) return;
    int start = g_rowstart[node];
    int end = start + g_cnt[node];
    float ax = 0.f, ay = 0.f, denom = 0.f;
    for (int j = start; j < end; j++) {
        int c = g_colp[j];          // broadcast
        float ex = g_expp[j];       // broadcast
        float2 v = *(const float2*)&g_Wh[(size_t)c * OUT_DIM + lane * 2];
        ax += ex * v.x;
        ay += ex * v.y;
        denom += ex;
    }
    float inv = 1.f / (denom + 1e-10f);
    ((float2*)(out + (size_t)node * OUT_DIM))[lane] = make_float2(ax * inv, ay * inv);
}

// ---------------- launch ------------------------------------------------------
extern "C" void kernel_launch(void* const* d_in, const int* in_sizes, int n_in,
                              void* d_out, int out_size) {
    const float* h = (const float*)d_in[0];
    const int* row = (const int*)d_in[1];
    const int* col = (const int*)d_in[2];
    const float* W = (const float*)d_in[3];
    const float* a = (const float*)d_in[4];
    float* out = (float*)d_out;

    int nscan = (N_NODES + 1023) / 1024;           // 98

    k_init<<<(N_NODES + 255) / 256, 256>>>();
    k_gemm<<<(N_NODES + NODE_TILE - 1) / NODE_TILE, K1_BLOCK>>>(h, W, a);
    k_hist<<<N_EDGES / 256, 256>>>(row);
    k_scan1<<<nscan, 1024>>>();
    k_scan2<<<1, 32>>>(nscan);
    k_scan3<<<(N_NODES + 255) / 256, 256>>>();
    k_fill<<<N_EDGES / 256, 256>>>(row, col);
    k_accum<<<(N_NODES * 32 + 255) / 256, 256>>>(out);
}

// round 5
// speedup vs baseline: 2.2007x; 1.1537x over previous
#include <cuda_runtime.h>

#define N_NODES 100000
#define N_EDGES 1600000
#define IN_DIM 128
#define OUT_DIM 64
#define NEG_SLOPE 0.2f

// ---------------- scratch (device globals: no allocations allowed) ----------
__device__ __align__(16) float g_Wh[N_NODES * OUT_DIM];   // 25.6 MB
__device__ float g_ssrc[N_NODES];
__device__ float g_sdst[N_NODES];
__device__ int   g_cnt[N_NODES];       // degree (by row)
__device__ int   g_rowstart[N_NODES];  // CSR offsets (exclusive scan of cnt)
__device__ int   g_cursor[N_NODES];    // fill cursors
__device__ int   g_bsum[128];          // block sums for scan
__device__ __align__(16) float2 g_pack[N_EDGES];  // (col-as-bits, exp), row-sorted

// ---------------- K0: zero histogram ----------------------------------------
__global__ void k_init() {
    int i = blockIdx.x * blockDim.x + threadIdx.x;
    if (i < N_NODES) g_cnt[i] = 0;
}

// ---------------- K1: fused [Wh = h @ W + s_src/s_dst]  and  [row histogram] --
// Blocks [0, GEMM_BLOCKS): GEMM, tile of 256 nodes, thread = 8 nodes x 8 outs.
// Blocks [GEMM_BLOCKS, +HIST_BLOCKS): histogram of row.
#define K1_BLOCK 256
#define NODE_TILE 256
#define KCH 8
#define GEMM_BLOCKS ((N_NODES + NODE_TILE - 1) / NODE_TILE)   // 391
#define HIST_BLOCKS (N_EDGES / 256)                           // 6250

__global__ __launch_bounds__(K1_BLOCK)
void k_gemm_hist(const float* __restrict__ h, const float* __restrict__ W,
                 const float* __restrict__ a, const int* __restrict__ row) {
    __shared__ __align__(16) float Ws[IN_DIM * OUT_DIM];      // 32 KB
    __shared__ float hs[NODE_TILE * (KCH + 1)];               // 9 KB
    __shared__ float as[2 * OUT_DIM];

    int tid = threadIdx.x;

    if (blockIdx.x >= GEMM_BLOCKS) {
        // -------- histogram part --------
        int e = (blockIdx.x - GEMM_BLOCKS) * K1_BLOCK + tid;
        if (e < N_EDGES) atomicAdd(&g_cnt[row[e]], 1);
        return;
    }

    // -------- GEMM part --------
    for (int i = tid; i < IN_DIM * OUT_DIM; i += K1_BLOCK) Ws[i] = W[i];
    if (tid < 2 * OUT_DIM) as[tid] = a[tid];

    int base = blockIdx.x * NODE_TILE;
    int nr = tid >> 3;             // 0..31
    int jc = (tid & 7) * 8;        // 0..56

    float acc[8][8];
#pragma unroll
    for (int i = 0; i < 8; i++)
#pragma unroll
        for (int q = 0; q < 8; q++) acc[i][q] = 0.f;

    for (int k0 = 0; k0 < IN_DIM; k0 += KCH) {
        __syncthreads();
        for (int i = tid; i < NODE_TILE * KCH; i += K1_BLOCK) {
            int nl = i >> 3, kk = i & 7;
            int gn = base + nl;
            hs[nl * (KCH + 1) + kk] = (gn < N_NODES) ? h[(size_t)gn * IN_DIM + k0 + kk] : 0.f;
        }
        __syncthreads();
#pragma unroll
        for (int kk = 0; kk < KCH; kk++) {
            float4 w0 = *(const float4*)&Ws[(k0 + kk) * OUT_DIM + jc];
            float4 w1 = *(const float4*)&Ws[(k0 + kk) * OUT_DIM + jc + 4];
#pragma unroll
            for (int i = 0; i < 8; i++) {
                float hk = hs[(nr + 32 * i) * (KCH + 1) + kk];
                acc[i][0] += hk * w0.x; acc[i][1] += hk * w0.y;
                acc[i][2] += hk * w0.z; acc[i][3] += hk * w0.w;
                acc[i][4] += hk * w1.x; acc[i][5] += hk * w1.y;
                acc[i][6] += hk * w1.z; acc[i][7] += hk * w1.w;
            }
        }
    }

#pragma unroll
    for (int i = 0; i < 8; i++) {
        int n = base + nr + 32 * i;
        float ps = 0.f, pd = 0.f;
#pragma unroll
        for (int q = 0; q < 8; q++) {
            ps += acc[i][q] * as[jc + q];
            pd += acc[i][q] * as[OUT_DIM + jc + q];
        }
        // reduce across the 8 consecutive lanes sharing this node
        for (int off = 4; off > 0; off >>= 1) {
            ps += __shfl_down_sync(0xFFFFFFFFu, ps, off, 8);
            pd += __shfl_down_sync(0xFFFFFFFFu, pd, off, 8);
        }
        if (n < N_NODES) {
            *(float4*)&g_Wh[(size_t)n * OUT_DIM + jc] =
                make_float4(acc[i][0], acc[i][1], acc[i][2], acc[i][3]);
            *(float4*)&g_Wh[(size_t)n * OUT_DIM + jc + 4] =
                make_float4(acc[i][4], acc[i][5], acc[i][6], acc[i][7]);
            if ((tid & 7) == 0) { g_ssrc[n] = ps; g_sdst[n] = pd; }
        }
    }
}

// ---------------- K3a: per-block inclusive scan -------------------------------
__global__ __launch_bounds__(1024)
void k_scan1() {
    __shared__ int sh[1024];
    int i = blockIdx.x * 1024 + threadIdx.x;
    int v = (i < N_NODES) ? g_cnt[i] : 0;
    sh[threadIdx.x] = v;
    __syncthreads();
    for (int off = 1; off < 1024; off <<= 1) {
        int t = (threadIdx.x >= off) ? sh[threadIdx.x - off] : 0;
        __syncthreads();
        sh[threadIdx.x] += t;
        __syncthreads();
    }
    if (i < N_NODES) g_rowstart[i] = sh[threadIdx.x];   // inclusive, block-local
    if (threadIdx.x == 1023) g_bsum[blockIdx.x] = sh[1023];
}

// ---------------- K3b: scan the 98 block sums (exclusive) ---------------------
__global__ void k_scan2(int nblocks) {
    if (threadIdx.x == 0 && blockIdx.x == 0) {
        int run = 0;
        for (int b = 0; b < nblocks; b++) {
            int t = g_bsum[b];
            g_bsum[b] = run;
            run += t;
        }
    }
}

// ---------------- K3c: finalize exclusive offsets + cursors -------------------
__global__ void k_scan3() {
    int i = blockIdx.x * blockDim.x + threadIdx.x;
    if (i >= N_NODES) return;
    int start = g_rowstart[i] - g_cnt[i] + g_bsum[i >> 10];
    g_rowstart[i] = start;
    g_cursor[i] = start;
}

// ---------------- K4: compute exp(e), fill row-sorted packed (col, exp) -------
__global__ void k_fill(const int* __restrict__ row,
                       const int* __restrict__ col) {
    int e = blockIdx.x * blockDim.x + threadIdx.x;
    if (e >= N_EDGES) return;
    int r = row[e], c = col[e];
    float x = g_ssrc[r] + g_sdst[c];
    float ev = x > 0.f ? x : NEG_SLOPE * x;
    float ex = __expf(ev);          // max-shift cancels in alpha; |ev| small
    int pos = atomicAdd(&g_cursor[r], 1);
    g_pack[pos] = make_float2(__int_as_float(c), ex);
}

// ---------------- K5: warp-per-node gather accumulation (no atomics) ----------
__global__ __launch_bounds__(256)
void k_accum(float* __restrict__ out) {
    int node = (blockIdx.x * blockDim.x + threadIdx.x) >> 5;
    int lane = threadIdx.x & 31;
    if (node >= N_NODES) return;
    int start = g_rowstart[node];
    int end = start + g_cnt[node];
    float ax = 0.f, ay = 0.f, denom = 0.f;
    int j = start;
    for (; j + 1 < end; j += 2) {
        float2 p0 = g_pack[j];
        float2 p1 = g_pack[j + 1];
        int c0 = __float_as_int(p0.x);
        int c1 = __float_as_int(p1.x);
        float2 v0 = *(const float2*)&g_Wh[(size_t)c0 * OUT_DIM + lane * 2];
        float2 v1 = *(const float2*)&g_Wh[(size_t)c1 * OUT_DIM + lane * 2];
        ax += p0.y * v0.x; ay += p0.y * v0.y;
        ax += p1.y * v1.x; ay += p1.y * v1.y;
        denom += p0.y + p1.y;
    }
    if (j < end) {
        float2 p0 = g_pack[j];
        int c0 = __float_as_int(p0.x);
        float2 v0 = *(const float2*)&g_Wh[(size_t)c0 * OUT_DIM + lane * 2];
        ax += p0.y * v0.x; ay += p0.y * v0.y;
        denom += p0.y;
    }
    float inv = 1.f / (denom + 1e-10f);
    ((float2*)(out + (size_t)node * OUT_DIM))[lane] = make_float2(ax * inv, ay * inv);
}

// ---------------- launch ------------------------------------------------------
extern "C" void kernel_launch(void* const* d_in, const int* in_sizes, int n_in,
                              void* d_out, int out_size) {
    const float* h = (const float*)d_in[0];
    const int* row = (const int*)d_in[1];
    const int* col = (const int*)d_in[2];
    const float* W = (const float*)d_in[3];
    const float* a = (const float*)d_in[4];
    float* out = (float*)d_out;

    int nscan = (N_NODES + 1023) / 1024;           // 98

    k_init<<<(N_NODES + 255) / 256, 256>>>();
    k_gemm_hist<<<GEMM_BLOCKS + HIST_BLOCKS, K1_BLOCK>>>(h, W, a, row);
    k_scan1<<<nscan, 1024>>>();
    k_scan2<<<1, 32>>>(nscan);
    k_scan3<<<(N_NODES + 255) / 256, 256>>>();
    k_fill<<<N_EDGES / 256, 256>>>(row, col);
    k_accum<<<(N_NODES * 32 + 255) / 256, 256>>>(out);
}